// round 12
// baseline (speedup 1.0000x reference)
#include <cuda_runtime.h>

#define BATCH 16
#define HH 512
#define WW 512
#define HWSZ (HH * WW)
#define TR 8

// ---- scratch (no allocations allowed; zero-initialized at module load) ----
// g_phase[b][0][k] = sum of de_h over pixels in columns with col%8==k (cols 0..510)
// g_phase[b][1][k] = sum of de_v over pixels in rows    with row%8==k (rows 0..510)
__device__ float g_phase[BATCH][2][8];
__device__ unsigned int g_done[BATCH];            // per-batch accum-completion tickets
__device__ __align__(16) int g_dec[BATCH][4];     // kh, bh, kv, bv (overwritten every run)

__device__ __forceinline__ float lum1(const float* p) {
    return 0.299f * p[0] + 0.587f * p[HWSZ] + 0.114f * p[2 * HWSZ];
}
__device__ __forceinline__ float2 lum2(float2 c0, float2 c1, float2 c2) {
    float2 l;
    l.x = 0.299f * c0.x + 0.587f * c1.x + 0.114f * c2.x;
    l.y = 0.299f * c0.y + 0.587f * c1.y + 0.114f * c2.y;
    return l;
}
// clipped excess: max(|t0-t1| - |r0-r1|, 0)
__device__ __forceinline__ float dexc(float t0, float t1, float r0, float r1) {
    return fmaxf(fabsf(t0 - t1) - fabsf(r0 - r1), 0.0f);
}

// -------------------------------------------------------------------------
// Kernel 1: streaming reduction into phase bins (proven R11 body) + ticket
// tail: the LAST accum block of each batch computes the decision, writes
// g_dec[b], and zeroes the bins + ticket for the next graph replay.
// grid: BATCH * 64 tiles * 8 strips = 8192 warps, 8 warps/block
//       (64 blocks per batch -> ticket target 64).
// -------------------------------------------------------------------------
__global__ __launch_bounds__(256) void jb_accum_kernel(
    const float* __restrict__ ref, const float* __restrict__ tgt)
{
    const int t     = threadIdx.x;
    const int gw    = blockIdx.x * 8 + (t >> 5);
    const int lane  = t & 31;
    const int b     = gw >> 9;            // 512 warps per batch; whole block same b
    const int rem   = gw & 511;
    const int tile  = rem >> 3;
    const int strip = rem & 7;
    const int r0    = tile * TR;          // multiple of 8
    const int c0    = strip * 64 + lane * 2;

    __shared__ float s_ph[2][8];
    if (t < 16) s_ph[t >> 3][t & 7] = 0.0f;
    __syncthreads();

    const float* rB = ref + (size_t)b * 3 * HWSZ;
    const float* tB = tgt + (size_t)b * 3 * HWSZ;

    const bool bnd_load = (lane == 31) && (strip < 7);   // col c0+2 in next strip
    const bool bnd_skip = (lane == 31) && (strip == 7);  // col 511: no right neighbor

    float2 cacc = make_float2(0.f, 0.f);
    float2 plr, plt;

    #pragma unroll 3
    for (int i = 0; i <= TR; ++i) {
        const int r = min(r0 + i, HH - 1);       // clamp phantom row (dv==0 there)
        const float* rp = rB + (size_t)r * WW + c0;
        const float* tp = tB + (size_t)r * WW + c0;
        float2 rc0 = *reinterpret_cast<const float2*>(rp);
        float2 rc1 = *reinterpret_cast<const float2*>(rp + HWSZ);
        float2 rc2 = *reinterpret_cast<const float2*>(rp + 2 * HWSZ);
        float2 tc0 = *reinterpret_cast<const float2*>(tp);
        float2 tc1 = *reinterpret_cast<const float2*>(tp + HWSZ);
        float2 tc2 = *reinterpret_cast<const float2*>(tp + 2 * HWSZ);
        float2 lr = lum2(rc0, rc1, rc2);
        float2 lt = lum2(tc0, tc1, tc2);

        if (i < TR) {
            float nr = __shfl_down_sync(0xffffffffu, lr.x, 1);
            float nt = __shfl_down_sync(0xffffffffu, lt.x, 1);
            if (bnd_load) {                  // boundary luminance (col c0+2)
                nr = lum1(rp + 2);
                nt = lum1(tp + 2);
            }
            cacc.x += dexc(lt.x, lt.y, lr.x, lr.y);
            if (!bnd_skip)
                cacc.y += dexc(lt.y, nt, lr.y, nr);
        }

        if (i > 0) {
            float dv = dexc(plt.x, lt.x, plr.x, lr.x)
                     + dexc(plt.y, lt.y, plr.y, lr.y);
            #pragma unroll
            for (int off = 16; off > 0; off >>= 1)
                dv += __shfl_down_sync(0xffffffffu, dv, off);
            if (lane == 0)
                atomicAdd(&s_ph[1][(i - 1) & 7], dv);  // row phase (r0%8==0)
        }
        plr = lr; plt = lt;
    }

    // ---- column phase reduce: sum the 4-lane groups (same (lane&3)) ----
    #pragma unroll
    for (int off = 4; off < 32; off <<= 1) {
        cacc.x += __shfl_xor_sync(0xffffffffu, cacc.x, off);
        cacc.y += __shfl_xor_sync(0xffffffffu, cacc.y, off);
    }
    if (lane < 4) {
        atomicAdd(&s_ph[0][lane * 2 + 0], cacc.x);   // phase 2*lane
        atomicAdd(&s_ph[0][lane * 2 + 1], cacc.y);   // phase 2*lane+1
    }
    __syncthreads();

    if (t < 16) {
        atomicAdd(&g_phase[b][t >> 3][t & 7], s_ph[t >> 3][t & 7]);
        __threadfence();                 // release: my bin atomics before my ticket
    }
    __syncthreads();

    // ---- ticket: last block of this batch decides + cleans ----
    __shared__ bool s_last;
    if (t == 0)
        s_last = (atomicAdd(&g_done[b], 1u) == 63u);
    __syncthreads();

    if (s_last) {
        __threadfence();                 // acquire: observe all blocks' bin atomics
        if (t < 16) s_ph[t >> 3][t & 7] = g_phase[b][t >> 3][t & 7];
        __syncthreads();

        if (t < 2) {
            float total = 0.0f;
            #pragma unroll
            for (int k = 0; k < 8; ++k) total += s_ph[t][k];
            float best_r = -1.0f;
            int   best_k = 0;
            #pragma unroll
            for (int k = 0; k < 8; ++k) {
                // phase sums are pixel sums; line-mean scale = /512
                float s     = s_ph[t][k] * (1.0f / 512.0f);
                float tot   = total * (1.0f / 512.0f);
                float cnt   = (k < 7) ? 64.0f : 63.0f;  // 511 lines: phases 0..6 have 64
                float a_k   = s / cnt;
                float bg    = (tot - s) / (511.0f - cnt);
                float ratio = a_k / (bg + 1e-8f);
                if (ratio > best_r) { best_r = ratio; best_k = k; }  // first-max
            }
            g_dec[b][t * 2 + 0] = best_k;
            g_dec[b][t * 2 + 1] = best_r > (1.0f / 0.35f);
        }
        // cleanup for the next graph replay (kernel boundary publishes g_dec)
        if (t < 16) g_phase[b][t >> 3][t & 7] = 0.0f;
        if (t == 0) g_done[b] = 0u;
    }
}

// -------------------------------------------------------------------------
// Kernel 2: PURE mask paint. One uniform 16B load of g_dec[b], 8 floats of
// mask logic, 2 x STG.128. No smem, no barriers, no fences, no tickets.
// grid: B*H*W/8 threads = 524288 -> 2048 blocks of 256.
// -------------------------------------------------------------------------
__global__ __launch_bounds__(256) void jb_write_kernel(float* __restrict__ out)
{
    const int idx = blockIdx.x * 256 + threadIdx.x;
    const int c8  = idx & 63;             // 64 chunks of 8 cols per row
    const int r   = (idx >> 6) & (HH - 1);
    const int b   = idx >> 15;            // 32768 threads per batch (block-aligned)

    const int4 d = *reinterpret_cast<const int4*>(&g_dec[b][0]);  // kh,bh,kv,bv
    const int kh = d.x, bh = d.y, kv = d.z, bv = d.w;

    const bool vrow = bv && ((r & 7) == kv) && (r < HH - 1);
    const bool tail = (c8 == 63);         // chunk containing col 511

    float4 o[2];
    float* op = reinterpret_cast<float*>(o);
    #pragma unroll
    for (int j = 0; j < 8; ++j) {
        bool vcol = bh && (j == kh) && !(tail && j == 7);
        op[j] = (vrow || vcol) ? 1.0f : 0.0f;
    }
    float4* dst = reinterpret_cast<float4*>(out + (size_t)idx * 8);
    dst[0] = o[0];
    dst[1] = o[1];
}

// -------------------------------------------------------------------------
extern "C" void kernel_launch(void* const* d_in, const int* in_sizes, int n_in,
                              void* d_out, int out_size)
{
    const float* ref = (const float*)d_in[0];
    const float* tgt = (const float*)d_in[1];
    float* out = (float*)d_out;

    // 16 batches * 64 tiles * 8 strips = 8192 warps -> 1024 blocks of 8 warps
    jb_accum_kernel<<<1024, 256>>>(ref, tgt);

    // 524288 threads, 8 floats each
    jb_write_kernel<<<2048, 256>>>(out);
}

// round 14
// speedup vs baseline: 1.2012x; 1.2012x over previous
#include <cuda_runtime.h>

#define BATCH 16
#define HH 512
#define WW 512
#define HWSZ (HH * WW)
#define TR 8

// ---- scratch (no allocations allowed; zero-initialized at module load) ----
// g_phase[b][0][k] = sum of de_h over pixels in columns with col%8==k (cols 0..510)
// g_phase[b][1][k] = sum of de_v over pixels in rows    with row%8==k (rows 0..510)
__device__ float g_phase[BATCH][2][8];
__device__ __align__(16) int g_dec[BATCH][4];     // kh, bh, kv, bv (rewritten every replay)

__device__ __forceinline__ float lum1(const float* p) {
    return 0.299f * p[0] + 0.587f * p[HWSZ] + 0.114f * p[2 * HWSZ];
}
__device__ __forceinline__ float2 lum2(float2 c0, float2 c1, float2 c2) {
    float2 l;
    l.x = 0.299f * c0.x + 0.587f * c1.x + 0.114f * c2.x;
    l.y = 0.299f * c0.y + 0.587f * c1.y + 0.114f * c2.y;
    return l;
}
// clipped excess: max(|t0-t1| - |r0-r1|, 0)
__device__ __forceinline__ float dexc(float t0, float t1, float r0, float r1) {
    return fmaxf(fabsf(t0 - t1) - fabsf(r0 - r1), 0.0f);
}

// -------------------------------------------------------------------------
// Kernel 1: PURE streaming reduction into phase bins (R11 body, nothing
// appended). Warp = 64-col x TR-row strip, float2 per lane.
// Block flushes its 16 smem bins with 16 global atomics. No fences, no
// tickets — kernel boundary publishes the bins to kernel 2.
// grid: BATCH * 64 tiles * 8 strips = 8192 warps, 8 warps/block.
// -------------------------------------------------------------------------
__global__ __launch_bounds__(256) void jb_accum_kernel(
    const float* __restrict__ ref, const float* __restrict__ tgt)
{
    const int t     = threadIdx.x;
    const int gw    = blockIdx.x * 8 + (t >> 5);
    const int lane  = t & 31;
    const int b     = gw >> 9;            // 512 warps per batch; whole block same b
    const int rem   = gw & 511;
    const int tile  = rem >> 3;
    const int strip = rem & 7;
    const int r0    = tile * TR;          // multiple of 8
    const int c0    = strip * 64 + lane * 2;

    __shared__ float s_ph[2][8];
    if (t < 16) s_ph[t >> 3][t & 7] = 0.0f;
    __syncthreads();

    const float* rB = ref + (size_t)b * 3 * HWSZ;
    const float* tB = tgt + (size_t)b * 3 * HWSZ;

    const bool bnd_load = (lane == 31) && (strip < 7);   // col c0+2 in next strip
    const bool bnd_skip = (lane == 31) && (strip == 7);  // col 511: no right neighbor

    float2 cacc = make_float2(0.f, 0.f);
    float2 plr, plt;

    #pragma unroll 3
    for (int i = 0; i <= TR; ++i) {
        const int r = min(r0 + i, HH - 1);       // clamp phantom row (dv==0 there)
        const float* rp = rB + (size_t)r * WW + c0;
        const float* tp = tB + (size_t)r * WW + c0;
        float2 rc0 = *reinterpret_cast<const float2*>(rp);
        float2 rc1 = *reinterpret_cast<const float2*>(rp + HWSZ);
        float2 rc2 = *reinterpret_cast<const float2*>(rp + 2 * HWSZ);
        float2 tc0 = *reinterpret_cast<const float2*>(tp);
        float2 tc1 = *reinterpret_cast<const float2*>(tp + HWSZ);
        float2 tc2 = *reinterpret_cast<const float2*>(tp + 2 * HWSZ);
        float2 lr = lum2(rc0, rc1, rc2);
        float2 lt = lum2(tc0, tc1, tc2);

        if (i < TR) {
            float nr = __shfl_down_sync(0xffffffffu, lr.x, 1);
            float nt = __shfl_down_sync(0xffffffffu, lt.x, 1);
            if (bnd_load) {                  // boundary luminance (col c0+2)
                nr = lum1(rp + 2);
                nt = lum1(tp + 2);
            }
            cacc.x += dexc(lt.x, lt.y, lr.x, lr.y);
            if (!bnd_skip)
                cacc.y += dexc(lt.y, nt, lr.y, nr);
        }

        if (i > 0) {
            float dv = dexc(plt.x, lt.x, plr.x, lr.x)
                     + dexc(plt.y, lt.y, plr.y, lr.y);
            #pragma unroll
            for (int off = 16; off > 0; off >>= 1)
                dv += __shfl_down_sync(0xffffffffu, dv, off);
            if (lane == 0)
                atomicAdd(&s_ph[1][(i - 1) & 7], dv);  // row phase (r0%8==0)
        }
        plr = lr; plt = lt;
    }

    // ---- column phase reduce: sum the 4-lane groups (same (lane&3)) ----
    #pragma unroll
    for (int off = 4; off < 32; off <<= 1) {
        cacc.x += __shfl_xor_sync(0xffffffffu, cacc.x, off);
        cacc.y += __shfl_xor_sync(0xffffffffu, cacc.y, off);
    }
    if (lane < 4) {
        atomicAdd(&s_ph[0][lane * 2 + 0], cacc.x);   // phase 2*lane
        atomicAdd(&s_ph[0][lane * 2 + 1], cacc.y);   // phase 2*lane+1
    }
    __syncthreads();

    if (t < 16)
        atomicAdd(&g_phase[b][t >> 3][t & 7], s_ph[t >> 3][t & 7]);
}

// -------------------------------------------------------------------------
// Kernel 2: decide + cleanup. ONE block of 256 threads.
// Threads 0..31 each own (batch, direction): read 8 bins, ratio test,
// write g_dec. Then the whole block zeroes all 256 bin floats for the
// next graph replay. Kernel boundaries provide all ordering — no fences.
// -------------------------------------------------------------------------
__global__ void jb_decide_kernel()
{
    const int t = threadIdx.x;

    if (t < 32) {
        const int b   = t >> 1;
        const int dir = t & 1;              // 0 = h (cols), 1 = v (rows)
        const float* bins = &g_phase[b][dir][0];

        float ph[8], total = 0.0f;
        #pragma unroll
        for (int k = 0; k < 8; ++k) { ph[k] = bins[k]; total += ph[k]; }

        float best_r = -1.0f;
        int   best_k = 0;
        #pragma unroll
        for (int k = 0; k < 8; ++k) {
            // phase sums are pixel sums; line-mean scale = /512
            float s     = ph[k] * (1.0f / 512.0f);
            float tot   = total * (1.0f / 512.0f);
            float cnt   = (k < 7) ? 64.0f : 63.0f;  // 511 lines: phases 0..6 have 64
            float a_k   = s / cnt;
            float bg    = (tot - s) / (511.0f - cnt);
            float ratio = a_k / (bg + 1e-8f);
            if (ratio > best_r) { best_r = ratio; best_k = k; }  // first-max (argmax)
        }
        g_dec[b][dir * 2 + 0] = best_k;
        g_dec[b][dir * 2 + 1] = best_r > (1.0f / 0.35f);
    }
    __syncthreads();                        // readers done before zeroing
    (&g_phase[0][0][0])[t] = 0.0f;          // 256 threads, 256 floats
}

// -------------------------------------------------------------------------
// Kernel 3: PURE mask paint. 512 blocks x 256 threads x 32 floats
// (8 x STG.128) — the per-block g_dec latency amortized over 128 B stores.
// No smem, no barriers, no fences.
// -------------------------------------------------------------------------
__global__ __launch_bounds__(256) void jb_write_kernel(float* __restrict__ out)
{
    const int idx = blockIdx.x * 256 + threadIdx.x;  // B*H*W/32 = 131072 threads
    const int cg  = idx & 15;             // 16 chunks of 32 cols per row
    const int r   = (idx >> 4) & (HH - 1);
    const int b   = idx >> 13;            // 8192 threads per batch (block-aligned)

    const int4 d = __ldg(reinterpret_cast<const int4*>(&g_dec[b][0]));  // kh,bh,kv,bv
    const int kh = d.x, bh = d.y, kv = d.z, bv = d.w;

    const bool vrow = bv && ((r & 7) == kv) && (r < HH - 1);
    const bool tail = (cg == 15);         // chunk containing col 511

    float4 o[8];
    float* op = reinterpret_cast<float*>(o);
    #pragma unroll
    for (int j = 0; j < 32; ++j) {
        bool vcol = bh && ((j & 7) == kh) && !(tail && j == 31);
        op[j] = (vrow || vcol) ? 1.0f : 0.0f;
    }
    float4* dst = reinterpret_cast<float4*>(out + (size_t)idx * 32);
    #pragma unroll
    for (int j = 0; j < 8; ++j) dst[j] = o[j];
}

// -------------------------------------------------------------------------
extern "C" void kernel_launch(void* const* d_in, const int* in_sizes, int n_in,
                              void* d_out, int out_size)
{
    const float* ref = (const float*)d_in[0];
    const float* tgt = (const float*)d_in[1];
    float* out = (float*)d_out;

    // 16 batches * 64 tiles * 8 strips = 8192 warps -> 1024 blocks of 8 warps
    jb_accum_kernel<<<1024, 256>>>(ref, tgt);

    jb_decide_kernel<<<1, 256>>>();

    jb_write_kernel<<<512, 256>>>(out);
}

// round 15
// speedup vs baseline: 1.2787x; 1.0645x over previous
#include <cuda_runtime.h>

#define BATCH 16
#define HH 512
#define WW 512
#define HWSZ (HH * WW)
#define TR 8

// ---- scratch (no allocations allowed; zero-initialized at module load) ----
__device__ float g_colsum[BATCH][WW];    // de_h summed over H, per column ([0..510] used)
__device__ float g_rowsum[BATCH][HH];    // de_v summed over W, per row ([0..510] + phantom 511)
__device__ __align__(16) int g_dec[BATCH][4];   // kh, bh, kv, bv (rewritten every replay)

// PDL: block until the programmatic predecessor grid has completed (implicit
// trigger at predecessor end -> its memory is visible after this returns).
__device__ __forceinline__ void gdc_wait() {
    asm volatile("griddepcontrol.wait;" ::: "memory");
}

__device__ __forceinline__ float lum1(const float* p) {
    return 0.299f * p[0] + 0.587f * p[HWSZ] + 0.114f * p[2 * HWSZ];
}
__device__ __forceinline__ float2 lum2(float2 c0, float2 c1, float2 c2) {
    float2 l;
    l.x = 0.299f * c0.x + 0.587f * c1.x + 0.114f * c2.x;
    l.y = 0.299f * c0.y + 0.587f * c1.y + 0.114f * c2.y;
    return l;
}
// clipped excess: max(|t0-t1| - |r0-r1|, 0)
__device__ __forceinline__ float dexc(float t0, float t1, float r0, float r1) {
    return fmaxf(fabsf(t0 - t1) - fabsf(r0 - r1), 0.0f);
}

// -------------------------------------------------------------------------
// Kernel 1: PURE barrier-free streaming reduction into LINE SUMS — exact
// body of the proven 22.5us version. Warp = 64-col x TR-row strip, float2
// per lane. No fences, no tickets.
// grid: BATCH * 64 tiles * 8 strips = 8192 warps, 8 warps/block.
// -------------------------------------------------------------------------
__global__ __launch_bounds__(256) void jb_accum_kernel(
    const float* __restrict__ ref, const float* __restrict__ tgt)
{
    const int gw    = blockIdx.x * 8 + (threadIdx.x >> 5);
    const int lane  = threadIdx.x & 31;
    const int b     = gw >> 9;            // 512 warps per batch
    const int rem   = gw & 511;
    const int tile  = rem >> 3;
    const int strip = rem & 7;
    const int r0    = tile * TR;
    const int c0    = strip * 64 + lane * 2;

    const float* rB = ref + (size_t)b * 3 * HWSZ;
    const float* tB = tgt + (size_t)b * 3 * HWSZ;

    const bool bnd_load = (lane == 31) && (strip < 7);   // col c0+2 in next strip
    const bool bnd_skip = (lane == 31) && (strip == 7);  // col 511: no right neighbor

    float2 cacc = make_float2(0.f, 0.f);
    float2 plr, plt;

    #pragma unroll 3
    for (int i = 0; i <= TR; ++i) {
        const int r = min(r0 + i, HH - 1);       // clamp phantom row (dv==0 there)
        const float* rp = rB + (size_t)r * WW + c0;
        const float* tp = tB + (size_t)r * WW + c0;
        float2 rc0 = *reinterpret_cast<const float2*>(rp);
        float2 rc1 = *reinterpret_cast<const float2*>(rp + HWSZ);
        float2 rc2 = *reinterpret_cast<const float2*>(rp + 2 * HWSZ);
        float2 tc0 = *reinterpret_cast<const float2*>(tp);
        float2 tc1 = *reinterpret_cast<const float2*>(tp + HWSZ);
        float2 tc2 = *reinterpret_cast<const float2*>(tp + 2 * HWSZ);
        float2 lr = lum2(rc0, rc1, rc2);
        float2 lt = lum2(tc0, tc1, tc2);

        if (i < TR) {
            float nr = __shfl_down_sync(0xffffffffu, lr.x, 1);
            float nt = __shfl_down_sync(0xffffffffu, lt.x, 1);
            if (bnd_load) {                  // boundary luminance (col c0+2)
                nr = lum1(rp + 2);
                nt = lum1(tp + 2);
            }
            cacc.x += dexc(lt.x, lt.y, lr.x, lr.y);
            if (!bnd_skip)
                cacc.y += dexc(lt.y, nt, lr.y, nr);
        }

        if (i > 0) {
            float dv = dexc(plt.x, lt.x, plr.x, lr.x)
                     + dexc(plt.y, lt.y, plr.y, lr.y);
            #pragma unroll
            for (int off = 16; off > 0; off >>= 1)
                dv += __shfl_down_sync(0xffffffffu, dv, off);
            if (lane == 0)
                atomicAdd(&g_rowsum[b][r0 + i - 1], dv);  // phantom -> idx 511 (unused)
        }
        plr = lr; plt = lt;
    }

    atomicAdd(&g_colsum[b][c0 + 0], cacc.x);
    atomicAdd(&g_colsum[b][c0 + 1], cacc.y);
}

// -------------------------------------------------------------------------
// Kernel 2: per-batch phase decision -> g_dec[b]. Also ZEROES the line
// sums it consumed (replay hygiene). PDL-waits on accum completion.
// grid: BATCH blocks x 128 threads (0..63 cols/h, 64..127 rows/v).
// -------------------------------------------------------------------------
__global__ void jb_decide_kernel()
{
    gdc_wait();                            // accum grid complete + visible

    const int b = blockIdx.x;
    const int t = threadIdx.x;

    __shared__ float ph[2][8];
    if (t < 16) ph[t >> 3][t & 7] = 0.0f;
    __syncthreads();

    const int grp = t >> 6;                // 0 = h (cols), 1 = v (rows)
    const int i0  = t & 63;
    float* src = grp ? g_rowsum[b] : g_colsum[b];

    float acc = 0.0f;
    for (int i = i0; i < 512; i += 64) {
        if (i < 511) acc += src[i] * (1.0f / 512.0f);   // line mean
        src[i] = 0.0f;                     // reset for next graph replay
    }
    atomicAdd(&ph[grp][i0 & 7], acc);
    __syncthreads();

    if (t < 2) {
        float total = 0.0f;
        #pragma unroll
        for (int k = 0; k < 8; ++k) total += ph[t][k];
        float best_r = -1.0f;
        int   best_k = 0;
        #pragma unroll
        for (int k = 0; k < 8; ++k) {
            float cnt   = (k < 7) ? 64.0f : 63.0f;   // 511 lines: phases 0..6 have 64
            float a_k   = ph[t][k] / cnt;
            float bg    = (total - ph[t][k]) / (511.0f - cnt);
            float ratio = a_k / (bg + 1e-8f);
            if (ratio > best_r) { best_r = ratio; best_k = k; }  // first-max (argmax)
        }
        g_dec[b][t * 2 + 0] = best_k;
        g_dec[b][t * 2 + 1] = best_r > (1.0f / 0.35f);
    }
}

// -------------------------------------------------------------------------
// Kernel 3: PURE mask paint. 512 blocks x 256 threads x 32 floats
// (8 x STG.128). PDL-waits on decide completion. No smem, no barriers.
// -------------------------------------------------------------------------
__global__ __launch_bounds__(256) void jb_write_kernel(float* __restrict__ out)
{
    const int idx = blockIdx.x * 256 + threadIdx.x;  // B*H*W/32 = 131072 threads
    const int cg  = idx & 15;             // 16 chunks of 32 cols per row
    const int r   = (idx >> 4) & (HH - 1);
    const int b   = idx >> 13;            // 8192 threads per batch (block-aligned)

    gdc_wait();                            // decide grid complete + g_dec visible

    const int4 d = __ldg(reinterpret_cast<const int4*>(&g_dec[b][0]));  // kh,bh,kv,bv
    const int kh = d.x, bh = d.y, kv = d.z, bv = d.w;

    const bool vrow = bv && ((r & 7) == kv) && (r < HH - 1);
    const bool tail = (cg == 15);         // chunk containing col 511

    float4 o[8];
    float* op = reinterpret_cast<float*>(o);
    #pragma unroll
    for (int j = 0; j < 32; ++j) {
        bool vcol = bh && ((j & 7) == kh) && !(tail && j == 31);
        op[j] = (vrow || vcol) ? 1.0f : 0.0f;
    }
    float4* dst = reinterpret_cast<float4*>(out + (size_t)idx * 32);
    #pragma unroll
    for (int j = 0; j < 8; ++j) dst[j] = o[j];
}

// -------------------------------------------------------------------------
extern "C" void kernel_launch(void* const* d_in, const int* in_sizes, int n_in,
                              void* d_out, int out_size)
{
    const float* ref = (const float*)d_in[0];
    const float* tgt = (const float*)d_in[1];
    float* out = (float*)d_out;

    // 16 batches * 64 tiles * 8 strips = 8192 warps -> 1024 blocks of 8 warps
    jb_accum_kernel<<<1024, 256>>>(ref, tgt);

    // PDL attribute: dependent grid may launch while predecessor drains;
    // griddepcontrol.wait inside the kernel provides the actual ordering.
    cudaLaunchAttribute attr[1];
    attr[0].id = cudaLaunchAttributeProgrammaticStreamSerialization;
    attr[0].val.programmaticStreamSerializationAllowed = 1;

    {
        cudaLaunchConfig_t cfg = {};
        cfg.gridDim  = dim3(BATCH);
        cfg.blockDim = dim3(128);
        cfg.stream   = 0;
        cfg.attrs    = attr;
        cfg.numAttrs = 1;
        cudaLaunchKernelEx(&cfg, jb_decide_kernel);
    }
    {
        cudaLaunchConfig_t cfg = {};
        cfg.gridDim  = dim3(512);
        cfg.blockDim = dim3(256);
        cfg.stream   = 0;
        cfg.attrs    = attr;
        cfg.numAttrs = 1;
        cudaLaunchKernelEx(&cfg, jb_write_kernel, out);
    }
}